// round 15
// baseline (speedup 1.0000x reference)
#include <cuda_runtime.h>
#include <cuda_fp16.h>
#include <math.h>
#include <cstdint>

// ---------------------------------------------------------------------------
// SpectroTFDecoder: pre-LN transformer decoder layer, fp32 I/O.
// GEMMs + attention on mma.sync fp16 tensor cores (fp32 accum).
// Weights in NATURAL [K,N] layout; B via ldmatrix.trans.
// tc_gemm: 4 warps, warp tile 64x64 (0.25 ldmatrix/MMA), cp.async 2-stage.
// QKV fused (N=3072); cross K/V fused (N=2048).
// Input order: 0 x, 1 src_x, 2 mask, 3 src_mask, 4-9 ln{1,2,3}_{g,b},
// 10-17 weights (sa_wq,sa_wk,sa_wv,sa_wo,ca_wq,ca_wk,ca_wv,ca_wo),
// 18-25 biases (same order), 26-29 ff_w1,ff_b1,ff_w2,ff_b2.
// ---------------------------------------------------------------------------

#define D_MODEL 1024
#define BATCH   4
#define TSEQ    1024
#define N_ROWS  (BATCH * TSEQ)
#define NHEAD   16
#define DHEAD   64
#define DFF_    4096
#define LN_EPS  1e-6f

// fp32 scratch (residual streams + fused biases)
__device__ float g_x1 [N_ROWS * D_MODEL];
__device__ float g_x2 [N_ROWS * D_MODEL];
__device__ float g_bqkv[3 * D_MODEL];
__device__ float g_bkv [2 * D_MODEL];

// fp16 scratch (weights natural [K,N], 1M-half segments for square ones)
#define WQ_OFF  0
#define WK_OFF  (1 << 20)
#define WV_OFF  (2 << 20)
#define WO_OFF  (3 << 20)
#define CQ_OFF  (4 << 20)
#define CK_OFF  (5 << 20)
#define CV_OFF  (6 << 20)
#define CO_OFF  (7 << 20)
#define W1_OFF  (8 << 20)
#define W2_OFF  (12 << 20)
__device__ __half g_wf16[16 << 20];   // weights, natural layout
__device__ __half g_af16[4 << 20];    // activation / ctx (D-wide)
__device__ __half g_sf16[4 << 20];    // src_x (persistent)
__device__ __half g_ff16[16 << 20];   // FF intermediate / ca-Q scratch
__device__ __half g_qkv [12 << 20];   // fused QKV / ca-KV

// ---------------------------------------------------------------------------
// asm helpers
// ---------------------------------------------------------------------------
__device__ __forceinline__ uint32_t smem_u32(const void* p) {
    uint32_t a;
    asm("{ .reg .u64 t; cvta.to.shared.u64 t, %1; cvt.u32.u64 %0, t; }"
        : "=r"(a) : "l"(p));
    return a;
}
__device__ __forceinline__ void ldm4(uint32_t* r, uint32_t a) {
    asm volatile("ldmatrix.sync.aligned.m8n8.x4.shared.b16 {%0,%1,%2,%3}, [%4];"
                 : "=r"(r[0]), "=r"(r[1]), "=r"(r[2]), "=r"(r[3]) : "r"(a));
}
__device__ __forceinline__ void ldm4t(uint32_t* r, uint32_t a) {
    asm volatile("ldmatrix.sync.aligned.m8n8.x4.trans.shared.b16 {%0,%1,%2,%3}, [%4];"
                 : "=r"(r[0]), "=r"(r[1]), "=r"(r[2]), "=r"(r[3]) : "r"(a));
}
__device__ __forceinline__ void mma16816(float* c, const uint32_t* a,
                                         const uint32_t* b) {
    asm volatile(
        "mma.sync.aligned.m16n8k16.row.col.f32.f16.f16.f32 "
        "{%0,%1,%2,%3},{%4,%5,%6,%7},{%8,%9},{%0,%1,%2,%3};"
        : "+f"(c[0]), "+f"(c[1]), "+f"(c[2]), "+f"(c[3])
        : "r"(a[0]), "r"(a[1]), "r"(a[2]), "r"(a[3]), "r"(b[0]), "r"(b[1]));
}
#define CPA16(dst, src) \
    asm volatile("cp.async.cg.shared.global [%0], [%1], 16;" :: "r"(dst), "l"(src))
#define CPA_COMMIT() asm volatile("cp.async.commit_group;" ::: "memory")
#define CPA_WAIT0()  asm volatile("cp.async.wait_group 0;"  ::: "memory")
#define CPA_WAIT1()  asm volatile("cp.async.wait_group 1;"  ::: "memory")

// ---------------------------------------------------------------------------
// batched elementwise fp32 -> fp16 convert: 20 slices of 1M elements.
// ---------------------------------------------------------------------------
struct CvtJob { const float* s[20]; __half* d[20]; };

__global__ __launch_bounds__(256)
void cvt_kernel(CvtJob j)
{
    const float* s = j.s[blockIdx.z];
    __half* d = j.d[blockIdx.z];
    const int i = (blockIdx.x * 256 + threadIdx.x) * 4;
    float4 a = *(const float4*)(s + i);
    *(__half2*)(d + i)     = __floats2half2_rn(a.x, a.y);
    *(__half2*)(d + i + 2) = __floats2half2_rn(a.z, a.w);
}

// ---------------------------------------------------------------------------
// bias concat: bqkv[3*1024] and bkv[2*1024]. grid = 20 x 256.
// ---------------------------------------------------------------------------
__global__ __launch_bounds__(256)
void catbias_kernel(const float* __restrict__ b0, const float* __restrict__ b1,
                    const float* __restrict__ b2, const float* __restrict__ b3,
                    const float* __restrict__ b4,
                    float* __restrict__ oqkv, float* __restrict__ okv)
{
    const int i = blockIdx.x * 256 + threadIdx.x;
    const int seg = i >> 10;
    const int off = i & 1023;
    switch (seg) {
        case 0: oqkv[i] = b0[off]; break;
        case 1: oqkv[i] = b1[off]; break;
        case 2: oqkv[i] = b2[off]; break;
        case 3: okv[off] = b3[off]; break;
        default: okv[1024 + off] = b4[off]; break;
    }
}

// ---------------------------------------------------------------------------
// LayerNorm fused with fp16 output.
// ---------------------------------------------------------------------------
__global__ __launch_bounds__(256)
void ln_f16_kernel(const float* __restrict__ x, const float* __restrict__ g,
                   const float* __restrict__ bta, __half* __restrict__ o)
{
    const int row = blockIdx.x;
    const int t = threadIdx.x;
    const float* xr = x + (size_t)row * D_MODEL;
    float4 xv = *(const float4*)(xr + t * 4);

    float s = xv.x + xv.y + xv.z + xv.w;
    __shared__ float red[8];
    #pragma unroll
    for (int off = 16; off > 0; off >>= 1) s += __shfl_xor_sync(~0u, s, off);
    if ((t & 31) == 0) red[t >> 5] = s;
    __syncthreads();
    float tot = 0.f;
    #pragma unroll
    for (int i = 0; i < 8; i++) tot += red[i];
    const float mu = tot * (1.f / 1024.f);

    const float dx0 = xv.x - mu, dx1 = xv.y - mu, dx2 = xv.z - mu, dx3 = xv.w - mu;
    float sq = dx0*dx0 + dx1*dx1 + dx2*dx2 + dx3*dx3;
    #pragma unroll
    for (int off = 16; off > 0; off >>= 1) sq += __shfl_xor_sync(~0u, sq, off);
    __syncthreads();
    if ((t & 31) == 0) red[t >> 5] = sq;
    __syncthreads();
    float tot2 = 0.f;
    #pragma unroll
    for (int i = 0; i < 8; i++) tot2 += red[i];
    const float sigma = sqrtf(tot2 * (1.f / 1024.f));
    const float inv = 1.f / (sigma + LN_EPS);

    float4 gv = *(const float4*)(g + t * 4);
    float4 bv = *(const float4*)(bta + t * 4);
    float o0 = dx0 * inv * gv.x + bv.x;
    float o1 = dx1 * inv * gv.y + bv.y;
    float o2 = dx2 * inv * gv.z + bv.z;
    float o3 = dx3 * inv * gv.w + bv.w;

    const size_t off = (size_t)row * D_MODEL + t * 4;
    *(__half2*)(o + off)     = __floats2half2_rn(o0, o1);
    *(__half2*)(o + off + 2) = __floats2half2_rn(o2, o3);
}

// ---------------------------------------------------------------------------
// Tensor-core GEMM: 128 threads / 4 warps (2x2), warp tile 64x64 (mt=4,nt=8),
// BK=32, cp.async 2-stage pipeline. A [M,K] row-major; B NATURAL [K,N-seg]
// row-major via ldmatrix.trans. Segmented B supports fused N.
// ---------------------------------------------------------------------------
#define TG_ROW 40
#define TG_TILE (128 * TG_ROW)
#define TB_ROW 136
#define TB_TILE (32 * TB_ROW)

template<bool RELU, bool RES, bool F16OUT>
__global__ __launch_bounds__(128, 2)
void tc_gemm(const __half* __restrict__ Af, const __half* __restrict__ Bf,
             int seg_shift, size_t seg_stride,
             const float* __restrict__ bias, const float* __restrict__ res,
             float* __restrict__ C, __half* __restrict__ Cf,
             int M, int N, int K)
{
    __shared__ __half As[2][TG_TILE];
    __shared__ __half Bs[2][TB_TILE];
    const uint32_t sbA = smem_u32(&As[0][0]);
    const uint32_t sbB = smem_u32(&Bs[0][0]);
    const int tid = threadIdx.x;
    const int lane = tid & 31;
    const int wid = tid >> 5;           // 0..3
    const int wm = wid >> 1;            // 0..1 (M)
    const int wn = wid & 1;             // 0..1 (N)
    const int bm = blockIdx.y * 128;
    const int bn = blockIdx.x * 128;

    const int ld_b = 1 << seg_shift;
    const __half* Bseg = Bf + (size_t)(bn >> seg_shift) * seg_stride;
    const int bn_l = bn & (ld_b - 1);

    // cp.async staging: A row = tid (64 B); B row = tid>>2, 64-B quarter
    const uint32_t soA = (uint32_t)(tid * TG_ROW) * 2;
    const char* gA = (const char*)(Af + (size_t)(bm + tid) * K);
    const int brow = tid >> 2;
    const int bcol = (tid & 3) * 32;
    const uint32_t soB = (uint32_t)(brow * TB_ROW + bcol) * 2;
    const char* gB = (const char*)(Bseg + (size_t)brow * ld_b + bn_l + bcol);
    const size_t bstep = (size_t)32 * ld_b * 2;   // bytes per k-tile

    auto issue = [&](int s, int kt) {
        const uint32_t ad = sbA + (uint32_t)s * (TG_TILE * 2) + soA;
        const char* ga = gA + kt * 64;
        CPA16(ad,      ga);
        CPA16(ad + 16, ga + 16);
        CPA16(ad + 32, ga + 32);
        CPA16(ad + 48, ga + 48);
        const uint32_t bd = sbB + (uint32_t)s * (TB_TILE * 2) + soB;
        const char* gb = gB + (size_t)kt * bstep;
        CPA16(bd,      gb);
        CPA16(bd + 16, gb + 16);
        CPA16(bd + 32, gb + 32);
        CPA16(bd + 48, gb + 48);
    };

    const uint32_t a_off = (uint32_t)((lane & 15) * TG_ROW * 2 + (lane >> 4) * 16);
    const uint32_t b_off = (uint32_t)((lane & 15) * TB_ROW * 2 + (lane >> 4) * 16);
    uint32_t aAddr[4], bAddr[4];
    #pragma unroll
    for (int mt = 0; mt < 4; mt++)
        aAddr[mt] = sbA + (uint32_t)((wm * 64 + mt * 16) * TG_ROW * 2) + a_off;
    #pragma unroll
    for (int ng = 0; ng < 4; ng++)
        bAddr[ng] = sbB + (uint32_t)((wn * 64 + ng * 16) * 2) + b_off;

    float acc[4][8][4];
    #pragma unroll
    for (int mt = 0; mt < 4; mt++)
        #pragma unroll
        for (int nt = 0; nt < 8; nt++)
            #pragma unroll
            for (int r = 0; r < 4; r++) acc[mt][nt][r] = 0.f;

    issue(0, 0);
    CPA_COMMIT();

    const int nk = K >> 5;
    for (int kt = 0; kt < nk; kt++) {
        const int cur = kt & 1;
        const bool more = (kt + 1 < nk);
        if (more) issue(cur ^ 1, kt + 1);
        CPA_COMMIT();
        if (more) { CPA_WAIT1(); } else { CPA_WAIT0(); }
        __syncthreads();

        const uint32_t stA = (uint32_t)cur * (TG_TILE * 2);
        const uint32_t stB = (uint32_t)cur * (TB_TILE * 2);
        #pragma unroll
        for (int ks = 0; ks < 2; ks++) {
            const uint32_t kbA = stA + ks * 32;
            const uint32_t kbB = stB + (uint32_t)(ks * 16 * TB_ROW * 2);
            uint32_t ah[4][4];
            #pragma unroll
            for (int mt = 0; mt < 4; mt++)
                ldm4(ah[mt], aAddr[mt] + kbA);
            #pragma unroll
            for (int ng = 0; ng < 4; ng++) {
                uint32_t bt[4];
                ldm4t(bt, bAddr[ng] + kbB);
                #pragma unroll
                for (int mt = 0; mt < 4; mt++) {
                    mma16816(acc[mt][2 * ng],     ah[mt], &bt[0]);
                    mma16816(acc[mt][2 * ng + 1], ah[mt], &bt[2]);
                }
            }
        }
        __syncthreads();   // reads done before this buffer is refilled
    }

    // epilogue
    const int er = lane >> 2;
    const int ec = (lane & 3) * 2;
    #pragma unroll
    for (int mt = 0; mt < 4; mt++) {
        const int row0 = bm + wm * 64 + mt * 16 + er;
        #pragma unroll
        for (int nt = 0; nt < 8; nt++) {
            const int col = bn + wn * 64 + nt * 8 + ec;
            float2 bv = *(const float2*)(bias + col);
            float v0 = acc[mt][nt][0] + bv.x;
            float v1 = acc[mt][nt][1] + bv.y;
            float v2 = acc[mt][nt][2] + bv.x;
            float v3 = acc[mt][nt][3] + bv.y;
            if (RELU) {
                v0 = fmaxf(v0, 0.f); v1 = fmaxf(v1, 0.f);
                v2 = fmaxf(v2, 0.f); v3 = fmaxf(v3, 0.f);
            }
            if (RES) {
                float2 r0 = *(const float2*)(res + (size_t)row0 * N + col);
                float2 r1 = *(const float2*)(res + (size_t)(row0 + 8) * N + col);
                v0 += r0.x; v1 += r0.y; v2 += r1.x; v3 += r1.y;
            }
            if (F16OUT) {
                *(__half2*)(Cf + (size_t)row0 * N + col)       = __floats2half2_rn(v0, v1);
                *(__half2*)(Cf + (size_t)(row0 + 8) * N + col) = __floats2half2_rn(v2, v3);
            } else {
                float2 o0 = {v0, v1};
                float2 o1 = {v2, v3};
                *(float2*)(C + (size_t)row0 * N + col) = o0;
                *(float2*)(C + (size_t)(row0 + 8) * N + col) = o1;
            }
        }
    }
}

// ---------------------------------------------------------------------------
// fp16 tensor-core flash attention (FA2 register scheme) with cp.async
// double-buffered K/V staging (round-12 version, unchanged).
// ---------------------------------------------------------------------------
#define QKST 72

__global__ __launch_bounds__(128)
void attn_tc_kernel(const __half* __restrict__ Qf, const __half* __restrict__ Kf,
                    const __half* __restrict__ Vf, __half* __restrict__ Of,
                    int ldq, int ldkv, int causal)
{
    __shared__ __half Qs[64 * QKST];
    __shared__ __half Ks[2][64 * QKST];
    __shared__ __half Vs[2][64 * QKST];
    const int qt = blockIdx.x;
    const int h  = blockIdx.y;
    const int b  = blockIdx.z;
    const int tid = threadIdx.x;
    const int lane = tid & 31;
    const int wid = tid >> 5;
    const size_t qrow0 = (size_t)b * TSEQ;

    const int sr = tid >> 1;
    const int shoff = (tid & 1) * 32;
    const uint32_t ksm[2] = {smem_u32(&Ks[0][0]), smem_u32(&Ks[1][0])};
    const uint32_t vsm[2] = {smem_u32(&Vs[0][0]), smem_u32(&Vs[1][0])};
    const uint32_t srowoff = (uint32_t)(sr * QKST + shoff) * 2;

    const int ktEnd = causal ? qt : (TSEQ / 64 - 1);

    auto issue_kv = [&](int s, int kt) {
        const size_t goff = (qrow0 + kt * 64 + sr) * (size_t)ldkv + h * DHEAD + shoff;
        const char* kg = (const char*)(Kf + goff);
        const char* vg = (const char*)(Vf + goff);
        const uint32_t kd = ksm[s] + srowoff;
        const uint32_t vd = vsm[s] + srowoff;
        CPA16(kd,      kg);
        CPA16(kd + 16, kg + 16);
        CPA16(kd + 32, kg + 32);
        CPA16(kd + 48, kg + 48);
        CPA16(vd,      vg);
        CPA16(vd + 16, vg + 16);
        CPA16(vd + 32, vg + 32);
        CPA16(vd + 48, vg + 48);
    };

    issue_kv(0, 0);
    CPA_COMMIT();
    {
        const __half2 sc = __floats2half2_rn(0.125f, 0.125f);
        const __half2* src = (const __half2*)(Qf + (qrow0 + qt * 64 + sr) * ldq
                                              + h * DHEAD + shoff);
        __half2* dst = (__half2*)(Qs + sr * QKST + shoff);
        #pragma unroll
        for (int i = 0; i < 16; i++) dst[i] = __hmul2(src[i], sc);
    }
    __syncthreads();

    const uint32_t a_off = (uint32_t)((lane & 15) * (QKST * 2) + (lane >> 4) * 16);
    const uint32_t b_off = (uint32_t)((((lane >> 4) << 3) + (lane & 7)) * (QKST * 2)
                                      + ((lane >> 3) & 1) * 16);

    uint32_t qfr[4][4];
    {
        const uint32_t qa = smem_u32(Qs) + (uint32_t)(wid * 16) * (QKST * 2) + a_off;
        #pragma unroll
        for (int ks = 0; ks < 4; ks++) ldm4(qfr[ks], qa + ks * 32);
    }

    float m0 = -INFINITY, m1 = -INFINITY, l0 = 0.f, l1 = 0.f;
    float ao[8][4];
    #pragma unroll
    for (int nt = 0; nt < 8; nt++)
        #pragma unroll
        for (int r = 0; r < 4; r++) ao[nt][r] = 0.f;

    const int gr = lane >> 2;
    const int gc = (lane & 3) * 2;
    const int row0 = qt * 64 + wid * 16 + gr;
    const int row1 = row0 + 8;

    for (int kt = 0; kt <= ktEnd; kt++) {
        const int buf = kt & 1;
        const bool more = (kt + 1 <= ktEnd);
        if (more) issue_kv(buf ^ 1, kt + 1);
        CPA_COMMIT();
        if (more) { CPA_WAIT1(); } else { CPA_WAIT0(); }
        __syncthreads();

        const uint32_t kbase = ksm[buf];
        const uint32_t vbase = vsm[buf];

        float s[8][4];
        #pragma unroll
        for (int nt = 0; nt < 8; nt++)
            #pragma unroll
            for (int r = 0; r < 4; r++) s[nt][r] = 0.f;
        #pragma unroll
        for (int g = 0; g < 4; g++) {
            #pragma unroll
            for (int ks = 0; ks < 4; ks++) {
                uint32_t bh[4];
                ldm4(bh, kbase + (uint32_t)(g * 16) * (QKST * 2) + b_off + ks * 32);
                mma16816(s[2 * g],     qfr[ks], &bh[0]);
                mma16816(s[2 * g + 1], qfr[ks], &bh[2]);
            }
        }

        const bool diag = causal && (kt == qt);
        float rmax0 = -INFINITY, rmax1 = -INFINITY;
        #pragma unroll
        for (int nt = 0; nt < 8; nt++) {
            if (diag) {
                const int c0 = kt * 64 + nt * 8 + gc;
                if (c0 > row0)     s[nt][0] = -INFINITY;
                if (c0 + 1 > row0) s[nt][1] = -INFINITY;
                if (c0 > row1)     s[nt][2] = -INFINITY;
                if (c0 + 1 > row1) s[nt][3] = -INFINITY;
            }
            rmax0 = fmaxf(rmax0, fmaxf(s[nt][0], s[nt][1]));
            rmax1 = fmaxf(rmax1, fmaxf(s[nt][2], s[nt][3]));
        }
        rmax0 = fmaxf(rmax0, __shfl_xor_sync(~0u, rmax0, 1));
        rmax0 = fmaxf(rmax0, __shfl_xor_sync(~0u, rmax0, 2));
        rmax1 = fmaxf(rmax1, __shfl_xor_sync(~0u, rmax1, 1));
        rmax1 = fmaxf(rmax1, __shfl_xor_sync(~0u, rmax1, 2));

        const float mn0 = fmaxf(m0, rmax0);
        const float mn1 = fmaxf(m1, rmax1);
        const float corr0 = __expf(m0 - mn0);
        const float corr1 = __expf(m1 - mn1);
        float rs0 = 0.f, rs1 = 0.f;
        uint32_t pf[8][2];
        #pragma unroll
        for (int nt = 0; nt < 8; nt++) {
            const float p0 = __expf(s[nt][0] - mn0);
            const float p1 = __expf(s[nt][1] - mn0);
            const float p2 = __expf(s[nt][2] - mn1);
            const float p3 = __expf(s[nt][3] - mn1);
            rs0 += p0 + p1;
            rs1 += p2 + p3;
            __half2 h01 = __floats2half2_rn(p0, p1);
            __half2 h23 = __floats2half2_rn(p2, p3);
            pf[nt][0] = *(uint32_t*)&h01;
            pf[nt][1] = *(uint32_t*)&h23;
        }
        rs0 += __shfl_xor_sync(~0u, rs0, 1);
        rs0 += __shfl_xor_sync(~0u, rs0, 2);
        rs1 += __shfl_xor_sync(~0u, rs1, 1);
        rs1 += __shfl_xor_sync(~0u, rs1, 2);
        l0 = l0 * corr0 + rs0;
        l1 = l1 * corr1 + rs1;
        m0 = mn0;
        m1 = mn1;
        #pragma unroll
        for (int nt = 0; nt < 8; nt++) {
            ao[nt][0] *= corr0; ao[nt][1] *= corr0;
            ao[nt][2] *= corr1; ao[nt][3] *= corr1;
        }

        #pragma unroll
        for (int kc = 0; kc < 4; kc++) {
            uint32_t pa[4] = {pf[2 * kc][0], pf[2 * kc][1],
                              pf[2 * kc + 1][0], pf[2 * kc + 1][1]};
            const uint32_t vrow = vbase + (uint32_t)(kc * 16) * (QKST * 2) + a_off;
            #pragma unroll
            for (int g = 0; g < 4; g++) {
                uint32_t bv[4];
                ldm4t(bv, vrow + g * 32);
                mma16816(ao[2 * g],     pa, &bv[0]);
                mma16816(ao[2 * g + 1], pa, &bv[2]);
            }
        }
        __syncthreads();
    }

    const float inv0 = 1.f / l0;
    const float inv1 = 1.f / l1;
    const size_t o0 = (qrow0 + row0) * D_MODEL + h * DHEAD;
    const size_t o1 = (qrow0 + row1) * D_MODEL + h * DHEAD;
    #pragma unroll
    for (int nt = 0; nt < 8; nt++) {
        const int col = nt * 8 + gc;
        *(__half2*)(Of + o0 + col) = __floats2half2_rn(ao[nt][0] * inv0, ao[nt][1] * inv0);
        *(__half2*)(Of + o1 + col) = __floats2half2_rn(ao[nt][2] * inv1, ao[nt][3] * inv1);
    }
}

// ---------------------------------------------------------------------------
// Host orchestration
// ---------------------------------------------------------------------------
extern "C" void kernel_launch(void* const* d_in, const int* in_sizes, int n_in,
                              void* d_out, int out_size)
{
    (void)in_sizes; (void)n_in; (void)out_size;
    const float* x     = (const float*)d_in[0];
    const float* src_x = (const float*)d_in[1];
    const float* ln1_g = (const float*)d_in[4];
    const float* ln1_b = (const float*)d_in[5];
    const float* ln2_g = (const float*)d_in[6];
    const float* ln2_b = (const float*)d_in[7];
    const float* ln3_g = (const float*)d_in[8];
    const float* ln3_b = (const float*)d_in[9];
    const float* W[8];
    for (int i = 0; i < 8; i++) W[i] = (const float*)d_in[10 + i];
    const float* Bv[8];
    for (int i = 0; i < 8; i++) Bv[i] = (const float*)d_in[18 + i];
    const float* ff_w1 = (const float*)d_in[26];
    const float* ff_b1 = (const float*)d_in[27];
    const float* ff_w2 = (const float*)d_in[28];
    const float* ff_b2 = (const float*)d_in[29];
    float* out = (float*)d_out;

    float *x1, *x2, *bqkv, *bkv;
    cudaGetSymbolAddress((void**)&x1, g_x1);
    cudaGetSymbolAddress((void**)&x2, g_x2);
    cudaGetSymbolAddress((void**)&bqkv, g_bqkv);
    cudaGetSymbolAddress((void**)&bkv,  g_bkv);
    __half *wf, *af, *sf, *ff, *qkv;
    cudaGetSymbolAddress((void**)&wf,  g_wf16);
    cudaGetSymbolAddress((void**)&af,  g_af16);
    cudaGetSymbolAddress((void**)&sf,  g_sf16);
    cudaGetSymbolAddress((void**)&ff,  g_ff16);
    cudaGetSymbolAddress((void**)&qkv, g_qkv);

    const dim3 gQKV(3 * D_MODEL / 128, N_ROWS / 128);   // (24, 32)
    const dim3 gKV (2 * D_MODEL / 128, N_ROWS / 128);   // (16, 32)
    const dim3 gD  (D_MODEL / 128, N_ROWS / 128);       // (8, 32)
    const dim3 gF1 (DFF_   / 128, N_ROWS / 128);        // (32, 32)
    const dim3 gAtt(TSEQ / 64, NHEAD, BATCH);
    const size_t SEG = (size_t)1 << 20;

    // ---- batched convert: 8 square weights + ff_w1 + ff_w2 + src_x ----
    {
        CvtJob j;
        for (int i = 0; i < 8; i++) { j.s[i] = W[i]; j.d[i] = wf + (i << 20); }
        for (int i = 0; i < 4; i++) {
            j.s[8  + i] = ff_w1 + i * (1 << 20); j.d[8  + i] = wf + W1_OFF + (i << 20);
            j.s[12 + i] = ff_w2 + i * (1 << 20); j.d[12 + i] = wf + W2_OFF + (i << 20);
            j.s[16 + i] = src_x + i * (1 << 20); j.d[16 + i] = sf + (i << 20);
        }
        dim3 gc(1024, 1, 20);
        cvt_kernel<<<gc, 256>>>(j);
    }
    catbias_kernel<<<20, 256>>>(Bv[0], Bv[1], Bv[2], Bv[5], Bv[6], bqkv, bkv);
    ln_f16_kernel<<<N_ROWS, 256>>>(x, ln1_g, ln1_b, af);

    // ---- self-attention block (fused QKV) ----
    tc_gemm<false, false, true><<<gQKV, 128>>>(af, wf + WQ_OFF, 10, SEG, bqkv, nullptr, nullptr, qkv, N_ROWS, 3 * D_MODEL, D_MODEL);
    attn_tc_kernel<<<gAtt, 128>>>(qkv, qkv + D_MODEL, qkv + 2 * D_MODEL, af,
                                  3 * D_MODEL, 3 * D_MODEL, 1);
    tc_gemm<false, true, false><<<gD, 128>>>(af, wf + WO_OFF, 10, SEG, Bv[3], x, x1, nullptr, N_ROWS, D_MODEL, D_MODEL);

    // ---- cross-attention block (fused KV) ----
    ln_f16_kernel<<<N_ROWS, 256>>>(x1, ln2_g, ln2_b, af);
    tc_gemm<false, false, true><<<gD, 128>>>(af, wf + CQ_OFF, 10, SEG, Bv[4], nullptr, nullptr, ff, N_ROWS, D_MODEL, D_MODEL);
    tc_gemm<false, false, true><<<gKV, 128>>>(sf, wf + CK_OFF, 10, SEG, bkv, nullptr, nullptr, qkv, N_ROWS, 2 * D_MODEL, D_MODEL);
    attn_tc_kernel<<<gAtt, 128>>>(ff, qkv, qkv + D_MODEL, af,
                                  D_MODEL, 2 * D_MODEL, 0);
    tc_gemm<false, true, false><<<gD, 128>>>(af, wf + CO_OFF, 10, SEG, Bv[7], x1, x2, nullptr, N_ROWS, D_MODEL, D_MODEL);

    // ---- FFN block ----
    ln_f16_kernel<<<N_ROWS, 256>>>(x2, ln3_g, ln3_b, af);
    tc_gemm<true, false, true><<<gF1, 128>>>(af, wf + W1_OFF, 12, SEG, ff_b1, nullptr, nullptr, ff, N_ROWS, DFF_, D_MODEL);
    tc_gemm<false, true, false><<<gD, 128>>>(ff, wf + W2_OFF, 10, SEG, ff_b2, x2, out, nullptr, N_ROWS, D_MODEL, DFF_);
}

// round 16
// speedup vs baseline: 1.1315x; 1.1315x over previous
#include <cuda_runtime.h>
#include <cuda_fp16.h>
#include <math.h>
#include <cstdint>

// ---------------------------------------------------------------------------
// SpectroTFDecoder: pre-LN transformer decoder layer, fp32 I/O.
// GEMMs + attention on mma.sync fp16 tensor cores (fp32 accum).
// Weights in NATURAL [K,N] layout; B via ldmatrix.trans (round-13 GEMM).
// QKV fused (N=3072); cross K/V fused (N=2048).
// Attention: FA2 register scheme, V via ldmatrix.trans, cp.async K/V double
// buffering, softmax exponentials via ex2.approx.f16x2 (2 exps per MUFU slot).
// Input order: 0 x, 1 src_x, 2 mask, 3 src_mask, 4-9 ln{1,2,3}_{g,b},
// 10-17 weights (sa_wq,sa_wk,sa_wv,sa_wo,ca_wq,ca_wk,ca_wv,ca_wo),
// 18-25 biases (same order), 26-29 ff_w1,ff_b1,ff_w2,ff_b2.
// ---------------------------------------------------------------------------

#define D_MODEL 1024
#define BATCH   4
#define TSEQ    1024
#define N_ROWS  (BATCH * TSEQ)
#define NHEAD   16
#define DHEAD   64
#define DFF_    4096
#define LN_EPS  1e-6f

// fp32 scratch (residual streams + fused biases)
__device__ float g_x1 [N_ROWS * D_MODEL];
__device__ float g_x2 [N_ROWS * D_MODEL];
__device__ float g_bqkv[3 * D_MODEL];
__device__ float g_bkv [2 * D_MODEL];

// fp16 scratch (weights natural [K,N], 1M-half segments for square ones)
#define WQ_OFF  0
#define WK_OFF  (1 << 20)
#define WV_OFF  (2 << 20)
#define WO_OFF  (3 << 20)
#define CQ_OFF  (4 << 20)
#define CK_OFF  (5 << 20)
#define CV_OFF  (6 << 20)
#define CO_OFF  (7 << 20)
#define W1_OFF  (8 << 20)
#define W2_OFF  (12 << 20)
__device__ __half g_wf16[16 << 20];   // weights, natural layout
__device__ __half g_af16[4 << 20];    // activation / ctx (D-wide)
__device__ __half g_sf16[4 << 20];    // src_x (persistent)
__device__ __half g_ff16[16 << 20];   // FF intermediate / ca-Q scratch
__device__ __half g_qkv [12 << 20];   // fused QKV / ca-KV

// ---------------------------------------------------------------------------
// asm helpers
// ---------------------------------------------------------------------------
__device__ __forceinline__ uint32_t smem_u32(const void* p) {
    uint32_t a;
    asm("{ .reg .u64 t; cvta.to.shared.u64 t, %1; cvt.u32.u64 %0, t; }"
        : "=r"(a) : "l"(p));
    return a;
}
__device__ __forceinline__ void ldm4(uint32_t* r, uint32_t a) {
    asm volatile("ldmatrix.sync.aligned.m8n8.x4.shared.b16 {%0,%1,%2,%3}, [%4];"
                 : "=r"(r[0]), "=r"(r[1]), "=r"(r[2]), "=r"(r[3]) : "r"(a));
}
__device__ __forceinline__ void ldm4t(uint32_t* r, uint32_t a) {
    asm volatile("ldmatrix.sync.aligned.m8n8.x4.trans.shared.b16 {%0,%1,%2,%3}, [%4];"
                 : "=r"(r[0]), "=r"(r[1]), "=r"(r[2]), "=r"(r[3]) : "r"(a));
}
__device__ __forceinline__ void mma16816(float* c, const uint32_t* a,
                                         const uint32_t* b) {
    asm volatile(
        "mma.sync.aligned.m16n8k16.row.col.f32.f16.f16.f32 "
        "{%0,%1,%2,%3},{%4,%5,%6,%7},{%8,%9},{%0,%1,%2,%3};"
        : "+f"(c[0]), "+f"(c[1]), "+f"(c[2]), "+f"(c[3])
        : "r"(a[0]), "r"(a[1]), "r"(a[2]), "r"(a[3]), "r"(b[0]), "r"(b[1]));
}
__device__ __forceinline__ uint32_t ex2_f16x2(uint32_t v) {
    asm("ex2.approx.f16x2 %0, %0;" : "+r"(v));
    return v;
}
#define CPA16(dst, src) \
    asm volatile("cp.async.cg.shared.global [%0], [%1], 16;" :: "r"(dst), "l"(src))
#define CPA_COMMIT() asm volatile("cp.async.commit_group;" ::: "memory")
#define CPA_WAIT0()  asm volatile("cp.async.wait_group 0;"  ::: "memory")
#define CPA_WAIT1()  asm volatile("cp.async.wait_group 1;"  ::: "memory")

// ---------------------------------------------------------------------------
// batched elementwise fp32 -> fp16 convert: 20 slices of 1M elements.
// ---------------------------------------------------------------------------
struct CvtJob { const float* s[20]; __half* d[20]; };

__global__ __launch_bounds__(256)
void cvt_kernel(CvtJob j)
{
    const float* s = j.s[blockIdx.z];
    __half* d = j.d[blockIdx.z];
    const int i = (blockIdx.x * 256 + threadIdx.x) * 4;
    float4 a = *(const float4*)(s + i);
    *(__half2*)(d + i)     = __floats2half2_rn(a.x, a.y);
    *(__half2*)(d + i + 2) = __floats2half2_rn(a.z, a.w);
}

// ---------------------------------------------------------------------------
// bias concat: bqkv[3*1024] and bkv[2*1024]. grid = 20 x 256.
// ---------------------------------------------------------------------------
__global__ __launch_bounds__(256)
void catbias_kernel(const float* __restrict__ b0, const float* __restrict__ b1,
                    const float* __restrict__ b2, const float* __restrict__ b3,
                    const float* __restrict__ b4,
                    float* __restrict__ oqkv, float* __restrict__ okv)
{
    const int i = blockIdx.x * 256 + threadIdx.x;
    const int seg = i >> 10;
    const int off = i & 1023;
    switch (seg) {
        case 0: oqkv[i] = b0[off]; break;
        case 1: oqkv[i] = b1[off]; break;
        case 2: oqkv[i] = b2[off]; break;
        case 3: okv[off] = b3[off]; break;
        default: okv[1024 + off] = b4[off]; break;
    }
}

// ---------------------------------------------------------------------------
// LayerNorm fused with fp16 output.
// ---------------------------------------------------------------------------
__global__ __launch_bounds__(256)
void ln_f16_kernel(const float* __restrict__ x, const float* __restrict__ g,
                   const float* __restrict__ bta, __half* __restrict__ o)
{
    const int row = blockIdx.x;
    const int t = threadIdx.x;
    const float* xr = x + (size_t)row * D_MODEL;
    float4 xv = *(const float4*)(xr + t * 4);

    float s = xv.x + xv.y + xv.z + xv.w;
    __shared__ float red[8];
    #pragma unroll
    for (int off = 16; off > 0; off >>= 1) s += __shfl_xor_sync(~0u, s, off);
    if ((t & 31) == 0) red[t >> 5] = s;
    __syncthreads();
    float tot = 0.f;
    #pragma unroll
    for (int i = 0; i < 8; i++) tot += red[i];
    const float mu = tot * (1.f / 1024.f);

    const float dx0 = xv.x - mu, dx1 = xv.y - mu, dx2 = xv.z - mu, dx3 = xv.w - mu;
    float sq = dx0*dx0 + dx1*dx1 + dx2*dx2 + dx3*dx3;
    #pragma unroll
    for (int off = 16; off > 0; off >>= 1) sq += __shfl_xor_sync(~0u, sq, off);
    __syncthreads();
    if ((t & 31) == 0) red[t >> 5] = sq;
    __syncthreads();
    float tot2 = 0.f;
    #pragma unroll
    for (int i = 0; i < 8; i++) tot2 += red[i];
    const float sigma = sqrtf(tot2 * (1.f / 1024.f));
    const float inv = 1.f / (sigma + LN_EPS);

    float4 gv = *(const float4*)(g + t * 4);
    float4 bv = *(const float4*)(bta + t * 4);
    float o0 = dx0 * inv * gv.x + bv.x;
    float o1 = dx1 * inv * gv.y + bv.y;
    float o2 = dx2 * inv * gv.z + bv.z;
    float o3 = dx3 * inv * gv.w + bv.w;

    const size_t off = (size_t)row * D_MODEL + t * 4;
    *(__half2*)(o + off)     = __floats2half2_rn(o0, o1);
    *(__half2*)(o + off + 2) = __floats2half2_rn(o2, o3);
}

// ---------------------------------------------------------------------------
// Tensor-core GEMM (round-13 proven version): fp16 single-MMA, register-
// staged double buffer. A [M,K] row-major; B NATURAL [K,N-seg] row-major via
// ldmatrix.trans. Segmented B supports fused N.
// BM=BN=128, BK=32, 8 warps (2x4), warp tile 64x32.
// ---------------------------------------------------------------------------
#define TG_ROW 40
#define TG_TILE (128 * TG_ROW)
#define TB_ROW 136
#define TB_TILE (32 * TB_ROW)

template<bool RELU, bool RES, bool F16OUT>
__global__ __launch_bounds__(256, 2)
void tc_gemm(const __half* __restrict__ Af, const __half* __restrict__ Bf,
             int seg_shift, size_t seg_stride,
             const float* __restrict__ bias, const float* __restrict__ res,
             float* __restrict__ C, __half* __restrict__ Cf,
             int M, int N, int K)
{
    __shared__ __half As[2][TG_TILE];
    __shared__ __half Bs[2][TB_TILE];
    const uint32_t sbA = smem_u32(&As[0][0]);
    const uint32_t sbB = smem_u32(&Bs[0][0]);
    const int tid = threadIdx.x;
    const int lane = tid & 31;
    const int wid = tid >> 5;
    const int wm = wid >> 2;
    const int wn = wid & 3;
    const int bm = blockIdx.y * 128;
    const int bn = blockIdx.x * 128;

    const int ld_b = 1 << seg_shift;
    const __half* Bseg = Bf + (size_t)(bn >> seg_shift) * seg_stride;
    const int bn_l = bn & (ld_b - 1);

    // A staging: thread -> (row 0..127, 16-elem half)
    const int srow = tid >> 1;
    const int shalf = (tid & 1) * 16;
    const uint32_t soA = (uint32_t)(srow * TG_ROW + shalf) * 2;
    const char* gA = (const char*)(Af + (size_t)(bm + srow) * K + shalf);

    // B staging: thread -> (k-row 0..31, 16-elem col chunk)
    const int brow = tid >> 3;
    const int bcol = (tid & 7) * 16;
    const uint32_t soB = (uint32_t)(brow * TB_ROW + bcol) * 2;
    const char* gB = (const char*)(Bseg + (size_t)brow * ld_b + bn_l + bcol);
    const size_t bstep = (size_t)32 * ld_b * 2;   // bytes per k-tile

    const uint32_t a_off = (uint32_t)((lane & 15) * TG_ROW * 2 + (lane >> 4) * 16);
    const uint32_t b_off = (uint32_t)((lane & 15) * TB_ROW * 2 + (lane >> 4) * 16);
    uint32_t aAddr[4], bAddr[2];
    #pragma unroll
    for (int mt = 0; mt < 4; mt++)
        aAddr[mt] = sbA + (uint32_t)((wm * 64 + mt * 16) * TG_ROW * 2) + a_off;
    #pragma unroll
    for (int ng = 0; ng < 2; ng++)
        bAddr[ng] = sbB + (uint32_t)((wn * 32 + ng * 16) * 2) + b_off;

    float acc[4][4][4];
    #pragma unroll
    for (int mt = 0; mt < 4; mt++)
        #pragma unroll
        for (int nt = 0; nt < 4; nt++)
            #pragma unroll
            for (int r = 0; r < 4; r++) acc[mt][nt][r] = 0.f;

    {
        char* tA = (char*)&As[0][0];
        char* tB = (char*)&Bs[0][0];
        *(uint4*)(tA + soA)      = *(const uint4*)gA;
        *(uint4*)(tA + soA + 16) = *(const uint4*)(gA + 16);
        *(uint4*)(tB + soB)      = *(const uint4*)gB;
        *(uint4*)(tB + soB + 16) = *(const uint4*)(gB + 16);
    }
    __syncthreads();

    const int nk = K >> 5;
    for (int kt = 0; kt < nk; kt++) {
        const int cur = kt & 1;
        const int nxt = cur ^ 1;
        const bool more = (kt + 1 < nk);
        uint4 pa0, pa1, pb0, pb1;
        if (more) {
            pa0 = *(const uint4*)(gA + (kt + 1) * 64);
            pa1 = *(const uint4*)(gA + (kt + 1) * 64 + 16);
            pb0 = *(const uint4*)(gB + (size_t)(kt + 1) * bstep);
            pb1 = *(const uint4*)(gB + (size_t)(kt + 1) * bstep + 16);
        }

        const uint32_t stA = (uint32_t)cur * (TG_TILE * 2);
        const uint32_t stB = (uint32_t)cur * (TB_TILE * 2);
        #pragma unroll
        for (int ks = 0; ks < 2; ks++) {
            const uint32_t kbA = stA + ks * 32;
            const uint32_t kbB = stB + (uint32_t)(ks * 16 * TB_ROW * 2);
            uint32_t ah[4][4], bt[2][4];
            #pragma unroll
            for (int mt = 0; mt < 4; mt++)
                ldm4(ah[mt], aAddr[mt] + kbA);
            #pragma unroll
            for (int ng = 0; ng < 2; ng++)
                ldm4t(bt[ng], bAddr[ng] + kbB);
            #pragma unroll
            for (int mt = 0; mt < 4; mt++) {
                #pragma unroll
                for (int nt = 0; nt < 4; nt++) {
                    const int ng = nt >> 1;
                    const int hf = (nt & 1) * 2;
                    mma16816(acc[mt][nt], ah[mt], &bt[ng][hf]);
                }
            }
        }

        if (more) {
            char* tA = (char*)&As[nxt][0];
            char* tB = (char*)&Bs[nxt][0];
            *(uint4*)(tA + soA)      = pa0;
            *(uint4*)(tA + soA + 16) = pa1;
            *(uint4*)(tB + soB)      = pb0;
            *(uint4*)(tB + soB + 16) = pb1;
        }
        __syncthreads();
    }

    const int er = lane >> 2;
    const int ec = (lane & 3) * 2;
    #pragma unroll
    for (int mt = 0; mt < 4; mt++) {
        const int row0 = bm + wm * 64 + mt * 16 + er;
        #pragma unroll
        for (int nt = 0; nt < 4; nt++) {
            const int col = bn + wn * 32 + nt * 8 + ec;
            float2 bv = *(const float2*)(bias + col);
            float v0 = acc[mt][nt][0] + bv.x;
            float v1 = acc[mt][nt][1] + bv.y;
            float v2 = acc[mt][nt][2] + bv.x;
            float v3 = acc[mt][nt][3] + bv.y;
            if (RELU) {
                v0 = fmaxf(v0, 0.f); v1 = fmaxf(v1, 0.f);
                v2 = fmaxf(v2, 0.f); v3 = fmaxf(v3, 0.f);
            }
            if (RES) {
                float2 r0 = *(const float2*)(res + (size_t)row0 * N + col);
                float2 r1 = *(const float2*)(res + (size_t)(row0 + 8) * N + col);
                v0 += r0.x; v1 += r0.y; v2 += r1.x; v3 += r1.y;
            }
            if (F16OUT) {
                *(__half2*)(Cf + (size_t)row0 * N + col)       = __floats2half2_rn(v0, v1);
                *(__half2*)(Cf + (size_t)(row0 + 8) * N + col) = __floats2half2_rn(v2, v3);
            } else {
                float2 o0 = {v0, v1};
                float2 o1 = {v2, v3};
                *(float2*)(C + (size_t)row0 * N + col) = o0;
                *(float2*)(C + (size_t)(row0 + 8) * N + col) = o1;
            }
        }
    }
}

// ---------------------------------------------------------------------------
// fp16 tensor-core flash attention with cp.async double-buffered K/V and
// ex2.approx.f16x2 softmax (2 exps per MUFU slot; result is directly the
// packed fp16 P fragment).
// ---------------------------------------------------------------------------
#define QKST 72
#define L2E 1.4426950408889634f

__global__ __launch_bounds__(128)
void attn_tc_kernel(const __half* __restrict__ Qf, const __half* __restrict__ Kf,
                    const __half* __restrict__ Vf, __half* __restrict__ Of,
                    int ldq, int ldkv, int causal)
{
    __shared__ __half Qs[64 * QKST];
    __shared__ __half Ks[2][64 * QKST];
    __shared__ __half Vs[2][64 * QKST];
    const int qt = blockIdx.x;
    const int h  = blockIdx.y;
    const int b  = blockIdx.z;
    const int tid = threadIdx.x;
    const int lane = tid & 31;
    const int wid = tid >> 5;
    const size_t qrow0 = (size_t)b * TSEQ;

    const int sr = tid >> 1;
    const int shoff = (tid & 1) * 32;
    const uint32_t ksm[2] = {smem_u32(&Ks[0][0]), smem_u32(&Ks[1][0])};
    const uint32_t vsm[2] = {smem_u32(&Vs[0][0]), smem_u32(&Vs[1][0])};
    const uint32_t srowoff = (uint32_t)(sr * QKST + shoff) * 2;

    const int ktEnd = causal ? qt : (TSEQ / 64 - 1);

    auto issue_kv = [&](int s, int kt) {
        const size_t goff = (qrow0 + kt * 64 + sr) * (size_t)ldkv + h * DHEAD + shoff;
        const char* kg = (const char*)(Kf + goff);
        const char* vg = (const char*)(Vf + goff);
        const uint32_t kd = ksm[s] + srowoff;
        const uint32_t vd = vsm[s] + srowoff;
        CPA16(kd,      kg);
        CPA16(kd + 16, kg + 16);
        CPA16(kd + 32, kg + 32);
        CPA16(kd + 48, kg + 48);
        CPA16(vd,      vg);
        CPA16(vd + 16, vg + 16);
        CPA16(vd + 32, vg + 32);
        CPA16(vd + 48, vg + 48);
    };

    issue_kv(0, 0);
    CPA_COMMIT();
    {
        const __half2 sc = __floats2half2_rn(0.125f, 0.125f);
        const __half2* src = (const __half2*)(Qf + (qrow0 + qt * 64 + sr) * ldq
                                              + h * DHEAD + shoff);
        __half2* dst = (__half2*)(Qs + sr * QKST + shoff);
        #pragma unroll
        for (int i = 0; i < 16; i++) dst[i] = __hmul2(src[i], sc);
    }
    __syncthreads();

    const uint32_t a_off = (uint32_t)((lane & 15) * (QKST * 2) + (lane >> 4) * 16);
    const uint32_t b_off = (uint32_t)((((lane >> 4) << 3) + (lane & 7)) * (QKST * 2)
                                      + ((lane >> 3) & 1) * 16);

    uint32_t qfr[4][4];
    {
        const uint32_t qa = smem_u32(Qs) + (uint32_t)(wid * 16) * (QKST * 2) + a_off;
        #pragma unroll
        for (int ks = 0; ks < 4; ks++) ldm4(qfr[ks], qa + ks * 32);
    }

    float m0 = -INFINITY, m1 = -INFINITY, l0 = 0.f, l1 = 0.f;
    float ao[8][4];
    #pragma unroll
    for (int nt = 0; nt < 8; nt++)
        #pragma unroll
        for (int r = 0; r < 4; r++) ao[nt][r] = 0.f;

    const int gr = lane >> 2;
    const int gc = (lane & 3) * 2;
    const int row0 = qt * 64 + wid * 16 + gr;
    const int row1 = row0 + 8;

    for (int kt = 0; kt <= ktEnd; kt++) {
        const int buf = kt & 1;
        const bool more = (kt + 1 <= ktEnd);
        if (more) issue_kv(buf ^ 1, kt + 1);
        CPA_COMMIT();
        if (more) { CPA_WAIT1(); } else { CPA_WAIT0(); }
        __syncthreads();

        const uint32_t kbase = ksm[buf];
        const uint32_t vbase = vsm[buf];

        float s[8][4];
        #pragma unroll
        for (int nt = 0; nt < 8; nt++)
            #pragma unroll
            for (int r = 0; r < 4; r++) s[nt][r] = 0.f;
        #pragma unroll
        for (int g = 0; g < 4; g++) {
            #pragma unroll
            for (int ks = 0; ks < 4; ks++) {
                uint32_t bh[4];
                ldm4(bh, kbase + (uint32_t)(g * 16) * (QKST * 2) + b_off + ks * 32);
                mma16816(s[2 * g],     qfr[ks], &bh[0]);
                mma16816(s[2 * g + 1], qfr[ks], &bh[2]);
            }
        }

        const bool diag = causal && (kt == qt);
        float rmax0 = -INFINITY, rmax1 = -INFINITY;
        #pragma unroll
        for (int nt = 0; nt < 8; nt++) {
            if (diag) {
                const int c0 = kt * 64 + nt * 8 + gc;
                if (c0 > row0)     s[nt][0] = -INFINITY;
                if (c0 + 1 > row0) s[nt][1] = -INFINITY;
                if (c0 > row1)     s[nt][2] = -INFINITY;
                if (c0 + 1 > row1) s[nt][3] = -INFINITY;
            }
            rmax0 = fmaxf(rmax0, fmaxf(s[nt][0], s[nt][1]));
            rmax1 = fmaxf(rmax1, fmaxf(s[nt][2], s[nt][3]));
        }
        rmax0 = fmaxf(rmax0, __shfl_xor_sync(~0u, rmax0, 1));
        rmax0 = fmaxf(rmax0, __shfl_xor_sync(~0u, rmax0, 2));
        rmax1 = fmaxf(rmax1, __shfl_xor_sync(~0u, rmax1, 1));
        rmax1 = fmaxf(rmax1, __shfl_xor_sync(~0u, rmax1, 2));

        const float mn0 = fmaxf(m0, rmax0);
        const float mn1 = fmaxf(m1, rmax1);
        const float corr0 = __expf(m0 - mn0);
        const float corr1 = __expf(m1 - mn1);
        float rs0 = 0.f, rs1 = 0.f;
        uint32_t pf[8][2];
        #pragma unroll
        for (int nt = 0; nt < 8; nt++) {
            // two exps per MUFU slot via fp16x2 ex2; output IS the P fragment
            __half2 ta = __floats2half2_rn((s[nt][0] - mn0) * L2E,
                                           (s[nt][1] - mn0) * L2E);
            __half2 tb = __floats2half2_rn((s[nt][2] - mn1) * L2E,
                                           (s[nt][3] - mn1) * L2E);
            const uint32_t ua = ex2_f16x2(*(uint32_t*)&ta);
            const uint32_t ub = ex2_f16x2(*(uint32_t*)&tb);
            pf[nt][0] = ua;
            pf[nt][1] = ub;
            float2 fa = __half22float2(*(__half2*)&ua);
            float2 fb = __half22float2(*(__half2*)&ub);
            rs0 += fa.x + fa.y;
            rs1 += fb.x + fb.y;
        }
        rs0 += __shfl_xor_sync(~0u, rs0, 1);
        rs0 += __shfl_xor_sync(~0u, rs0, 2);
        rs1 += __shfl_xor_sync(~0u, rs1, 1);
        rs1 += __shfl_xor_sync(~0u, rs1, 2);
        l0 = l0 * corr0 + rs0;
        l1 = l1 * corr1 + rs1;
        m0 = mn0;
        m1 = mn1;
        #pragma unroll
        for (int nt = 0; nt < 8; nt++) {
            ao[nt][0] *= corr0; ao[nt][1] *= corr0;
            ao[nt][2] *= corr1; ao[nt][3] *= corr1;
        }

        #pragma unroll
        for (int kc = 0; kc < 4; kc++) {
            uint32_t pa[4] = {pf[2 * kc][0], pf[2 * kc][1],
                              pf[2 * kc + 1][0], pf[2 * kc + 1][1]};
            const uint32_t vrow = vbase + (uint32_t)(kc * 16) * (QKST * 2) + a_off;
            #pragma unroll
            for (int g = 0; g < 4; g++) {
                uint32_t bv[4];
                ldm4t(bv, vrow + g * 32);
                mma16816(ao[2 * g],     pa, &bv[0]);
                mma16816(ao[2 * g + 1], pa, &bv[2]);
            }
        }
        __syncthreads();
    }

    const float inv0 = 1.f / l0;
    const float inv1 = 1.f / l1;
    const size_t o0 = (qrow0 + row0) * D_MODEL + h * DHEAD;
    const size_t o1 = (qrow0 + row1) * D_MODEL + h * DHEAD;
    #pragma unroll
    for (int nt = 0; nt < 8; nt++) {
        const int col = nt * 8 + gc;
        *(__half2*)(Of + o0 + col) = __floats2half2_rn(ao[nt][0] * inv0, ao[nt][1] * inv0);
        *(__half2*)(Of + o1 + col) = __floats2half2_rn(ao[nt][2] * inv1, ao[nt][3] * inv1);
    }
}

// ---------------------------------------------------------------------------
// Host orchestration
// ---------------------------------------------------------------------------
extern "C" void kernel_launch(void* const* d_in, const int* in_sizes, int n_in,
                              void* d_out, int out_size)
{
    (void)in_sizes; (void)n_in; (void)out_size;
    const float* x     = (const float*)d_in[0];
    const float* src_x = (const float*)d_in[1];
    const float* ln1_g = (const float*)d_in[4];
    const float* ln1_b = (const float*)d_in[5];
    const float* ln2_g = (const float*)d_in[6];
    const float* ln2_b = (const float*)d_in[7];
    const float* ln3_g = (const float*)d_in[8];
    const float* ln3_b = (const float*)d_in[9];
    const float* W[8];
    for (int i = 0; i < 8; i++) W[i] = (const float*)d_in[10 + i];
    const float* Bv[8];
    for (int i = 0; i < 8; i++) Bv[i] = (const float*)d_in[18 + i];
    const float* ff_w1 = (const float*)d_in[26];
    const float* ff_b1 = (const float*)d_in[27];
    const float* ff_w2 = (const float*)d_in[28];
    const float* ff_b2 = (const float*)d_in[29];
    float* out = (float*)d_out;

    float *x1, *x2, *bqkv, *bkv;
    cudaGetSymbolAddress((void**)&x1, g_x1);
    cudaGetSymbolAddress((void**)&x2, g_x2);
    cudaGetSymbolAddress((void**)&bqkv, g_bqkv);
    cudaGetSymbolAddress((void**)&bkv,  g_bkv);
    __half *wf, *af, *sf, *ff, *qkv;
    cudaGetSymbolAddress((void**)&wf,  g_wf16);
    cudaGetSymbolAddress((void**)&af,  g_af16);
    cudaGetSymbolAddress((void**)&sf,  g_sf16);
    cudaGetSymbolAddress((void**)&ff,  g_ff16);
    cudaGetSymbolAddress((void**)&qkv, g_qkv);

    const dim3 gQKV(3 * D_MODEL / 128, N_ROWS / 128);   // (24, 32)
    const dim3 gKV (2 * D_MODEL / 128, N_ROWS / 128);   // (16, 32)
    const dim3 gD  (D_MODEL / 128, N_ROWS / 128);       // (8, 32)
    const dim3 gF1 (DFF_   / 128, N_ROWS / 128);        // (32, 32)
    const dim3 gAtt(TSEQ / 64, NHEAD, BATCH);
    const size_t SEG = (size_t)1 << 20;

    // ---- batched convert: 8 square weights + ff_w1 + ff_w2 + src_x ----
    {
        CvtJob j;
        for (int i = 0; i < 8; i++) { j.s[i] = W[i]; j.d[i] = wf + (i << 20); }
        for (int i = 0; i < 4; i++) {
            j.s[8  + i] = ff_w1 + i * (1 << 20); j.d[8  + i] = wf + W1_OFF + (i << 20);
            j.s[12 + i] = ff_w2 + i * (1 << 20); j.d[12 + i] = wf + W2_OFF + (i << 20);
            j.s[16 + i] = src_x + i * (1 << 20); j.d[16 + i] = sf + (i << 20);
        }
        dim3 gc(1024, 1, 20);
        cvt_kernel<<<gc, 256>>>(j);
    }
    catbias_kernel<<<20, 256>>>(Bv[0], Bv[1], Bv[2], Bv[5], Bv[6], bqkv, bkv);
    ln_f16_kernel<<<N_ROWS, 256>>>(x, ln1_g, ln1_b, af);

    // ---- self-attention block (fused QKV) ----
    tc_gemm<false, false, true><<<gQKV, 256>>>(af, wf + WQ_OFF, 10, SEG, bqkv, nullptr, nullptr, qkv, N_ROWS, 3 * D_MODEL, D_MODEL);
    attn_tc_kernel<<<gAtt, 128>>>(qkv, qkv + D_MODEL, qkv + 2 * D_MODEL, af,
                                  3 * D_MODEL, 3 * D_MODEL, 1);
    tc_gemm<false, true, false><<<gD, 256>>>(af, wf + WO_OFF, 10, SEG, Bv[3], x, x1, nullptr, N_ROWS, D_MODEL, D_MODEL);

    // ---- cross-attention block (fused KV) ----
    ln_f16_kernel<<<N_ROWS, 256>>>(x1, ln2_g, ln2_b, af);
    tc_gemm<false, false, true><<<gD, 256>>>(af, wf + CQ_OFF, 10, SEG, Bv[4], nullptr, nullptr, ff, N_ROWS, D_MODEL, D_MODEL);
    tc_gemm<false, false, true><<<gKV, 256>>>(sf, wf + CK_OFF, 10, SEG, bkv, nullptr, nullptr, qkv, N_ROWS, 2 * D_MODEL, D_MODEL);
    attn_tc_kernel<<<gAtt, 128>>>(ff, qkv, qkv + D_MODEL, af,
                                  D_MODEL, 2 * D_MODEL, 0);
    tc_gemm<false, true, false><<<gD, 256>>>(af, wf + CO_OFF, 10, SEG, Bv[7], x1, x2, nullptr, N_ROWS, D_MODEL, D_MODEL);

    // ---- FFN block ----
    ln_f16_kernel<<<N_ROWS, 256>>>(x2, ln3_g, ln3_b, af);
    tc_gemm<true, false, true><<<gF1, 256>>>(af, wf + W1_OFF, 12, SEG, ff_b1, nullptr, nullptr, ff, N_ROWS, DFF_, D_MODEL);
    tc_gemm<false, true, false><<<gD, 256>>>(ff, wf + W2_OFF, 10, SEG, ff_b2, x2, out, nullptr, N_ROWS, D_MODEL, DFF_);
}

// round 17
// speedup vs baseline: 1.2086x; 1.0681x over previous
#include <cuda_runtime.h>
#include <cuda_fp16.h>
#include <math.h>
#include <cstdint>

// ---------------------------------------------------------------------------
// SpectroTFDecoder: pre-LN transformer decoder layer, fp32 I/O.
// GEMMs + attention on mma.sync fp16 tensor cores (fp32 accum).
// Weights in NATURAL [K,N] layout; B via ldmatrix.trans.
// tc_gemm: round-13 tiling (8 warps, 64x32 warp tile) with cp.async.cg
// staging (L1-bypass) to cut L1TEX wavefronts. QKV fused (N=3072); cross
// K/V fused (N=2048). Attention: FA2 + cp.async + ex2.approx.f16x2 softmax.
// Input order: 0 x, 1 src_x, 2 mask, 3 src_mask, 4-9 ln{1,2,3}_{g,b},
// 10-17 weights (sa_wq,sa_wk,sa_wv,sa_wo,ca_wq,ca_wk,ca_wv,ca_wo),
// 18-25 biases (same order), 26-29 ff_w1,ff_b1,ff_w2,ff_b2.
// ---------------------------------------------------------------------------

#define D_MODEL 1024
#define BATCH   4
#define TSEQ    1024
#define N_ROWS  (BATCH * TSEQ)
#define NHEAD   16
#define DHEAD   64
#define DFF_    4096
#define LN_EPS  1e-6f

// fp32 scratch (residual streams + fused biases)
__device__ float g_x1 [N_ROWS * D_MODEL];
__device__ float g_x2 [N_ROWS * D_MODEL];
__device__ float g_bqkv[3 * D_MODEL];
__device__ float g_bkv [2 * D_MODEL];

// fp16 scratch (weights natural [K,N], 1M-half segments for square ones)
#define WQ_OFF  0
#define WK_OFF  (1 << 20)
#define WV_OFF  (2 << 20)
#define WO_OFF  (3 << 20)
#define CQ_OFF  (4 << 20)
#define CK_OFF  (5 << 20)
#define CV_OFF  (6 << 20)
#define CO_OFF  (7 << 20)
#define W1_OFF  (8 << 20)
#define W2_OFF  (12 << 20)
__device__ __half g_wf16[16 << 20];   // weights, natural layout
__device__ __half g_af16[4 << 20];    // activation / ctx (D-wide)
__device__ __half g_sf16[4 << 20];    // src_x (persistent)
__device__ __half g_ff16[16 << 20];   // FF intermediate / ca-Q scratch
__device__ __half g_qkv [12 << 20];   // fused QKV / ca-KV

// ---------------------------------------------------------------------------
// asm helpers
// ---------------------------------------------------------------------------
__device__ __forceinline__ uint32_t smem_u32(const void* p) {
    uint32_t a;
    asm("{ .reg .u64 t; cvta.to.shared.u64 t, %1; cvt.u32.u64 %0, t; }"
        : "=r"(a) : "l"(p));
    return a;
}
__device__ __forceinline__ void ldm4(uint32_t* r, uint32_t a) {
    asm volatile("ldmatrix.sync.aligned.m8n8.x4.shared.b16 {%0,%1,%2,%3}, [%4];"
                 : "=r"(r[0]), "=r"(r[1]), "=r"(r[2]), "=r"(r[3]) : "r"(a));
}
__device__ __forceinline__ void ldm4t(uint32_t* r, uint32_t a) {
    asm volatile("ldmatrix.sync.aligned.m8n8.x4.trans.shared.b16 {%0,%1,%2,%3}, [%4];"
                 : "=r"(r[0]), "=r"(r[1]), "=r"(r[2]), "=r"(r[3]) : "r"(a));
}
__device__ __forceinline__ void mma16816(float* c, const uint32_t* a,
                                         const uint32_t* b) {
    asm volatile(
        "mma.sync.aligned.m16n8k16.row.col.f32.f16.f16.f32 "
        "{%0,%1,%2,%3},{%4,%5,%6,%7},{%8,%9},{%0,%1,%2,%3};"
        : "+f"(c[0]), "+f"(c[1]), "+f"(c[2]), "+f"(c[3])
        : "r"(a[0]), "r"(a[1]), "r"(a[2]), "r"(a[3]), "r"(b[0]), "r"(b[1]));
}
__device__ __forceinline__ uint32_t ex2_f16x2(uint32_t v) {
    asm("ex2.approx.f16x2 %0, %0;" : "+r"(v));
    return v;
}
#define CPA16(dst, src) \
    asm volatile("cp.async.cg.shared.global [%0], [%1], 16;" :: "r"(dst), "l"(src))
#define CPA_COMMIT() asm volatile("cp.async.commit_group;" ::: "memory")
#define CPA_WAIT0()  asm volatile("cp.async.wait_group 0;"  ::: "memory")
#define CPA_WAIT1()  asm volatile("cp.async.wait_group 1;"  ::: "memory")

// ---------------------------------------------------------------------------
// batched elementwise fp32 -> fp16 convert: 20 slices of 1M elements.
// ---------------------------------------------------------------------------
struct CvtJob { const float* s[20]; __half* d[20]; };

__global__ __launch_bounds__(256)
void cvt_kernel(CvtJob j)
{
    const float* s = j.s[blockIdx.z];
    __half* d = j.d[blockIdx.z];
    const int i = (blockIdx.x * 256 + threadIdx.x) * 4;
    float4 a = *(const float4*)(s + i);
    *(__half2*)(d + i)     = __floats2half2_rn(a.x, a.y);
    *(__half2*)(d + i + 2) = __floats2half2_rn(a.z, a.w);
}

// ---------------------------------------------------------------------------
// bias concat: bqkv[3*1024] and bkv[2*1024]. grid = 20 x 256.
// ---------------------------------------------------------------------------
__global__ __launch_bounds__(256)
void catbias_kernel(const float* __restrict__ b0, const float* __restrict__ b1,
                    const float* __restrict__ b2, const float* __restrict__ b3,
                    const float* __restrict__ b4,
                    float* __restrict__ oqkv, float* __restrict__ okv)
{
    const int i = blockIdx.x * 256 + threadIdx.x;
    const int seg = i >> 10;
    const int off = i & 1023;
    switch (seg) {
        case 0: oqkv[i] = b0[off]; break;
        case 1: oqkv[i] = b1[off]; break;
        case 2: oqkv[i] = b2[off]; break;
        case 3: okv[off] = b3[off]; break;
        default: okv[1024 + off] = b4[off]; break;
    }
}

// ---------------------------------------------------------------------------
// LayerNorm fused with fp16 output.
// ---------------------------------------------------------------------------
__global__ __launch_bounds__(256)
void ln_f16_kernel(const float* __restrict__ x, const float* __restrict__ g,
                   const float* __restrict__ bta, __half* __restrict__ o)
{
    const int row = blockIdx.x;
    const int t = threadIdx.x;
    const float* xr = x + (size_t)row * D_MODEL;
    float4 xv = *(const float4*)(xr + t * 4);

    float s = xv.x + xv.y + xv.z + xv.w;
    __shared__ float red[8];
    #pragma unroll
    for (int off = 16; off > 0; off >>= 1) s += __shfl_xor_sync(~0u, s, off);
    if ((t & 31) == 0) red[t >> 5] = s;
    __syncthreads();
    float tot = 0.f;
    #pragma unroll
    for (int i = 0; i < 8; i++) tot += red[i];
    const float mu = tot * (1.f / 1024.f);

    const float dx0 = xv.x - mu, dx1 = xv.y - mu, dx2 = xv.z - mu, dx3 = xv.w - mu;
    float sq = dx0*dx0 + dx1*dx1 + dx2*dx2 + dx3*dx3;
    #pragma unroll
    for (int off = 16; off > 0; off >>= 1) sq += __shfl_xor_sync(~0u, sq, off);
    __syncthreads();
    if ((t & 31) == 0) red[t >> 5] = sq;
    __syncthreads();
    float tot2 = 0.f;
    #pragma unroll
    for (int i = 0; i < 8; i++) tot2 += red[i];
    const float sigma = sqrtf(tot2 * (1.f / 1024.f));
    const float inv = 1.f / (sigma + LN_EPS);

    float4 gv = *(const float4*)(g + t * 4);
    float4 bv = *(const float4*)(bta + t * 4);
    float o0 = dx0 * inv * gv.x + bv.x;
    float o1 = dx1 * inv * gv.y + bv.y;
    float o2 = dx2 * inv * gv.z + bv.z;
    float o3 = dx3 * inv * gv.w + bv.w;

    const size_t off = (size_t)row * D_MODEL + t * 4;
    *(__half2*)(o + off)     = __floats2half2_rn(o0, o1);
    *(__half2*)(o + off + 2) = __floats2half2_rn(o2, o3);
}

// ---------------------------------------------------------------------------
// Tensor-core GEMM: round-13 tiling with cp.async.cg 2-stage staging
// (L1-bypass removes LDG read wavefronts from the binding L1 pipe).
// A [M,K] row-major; B NATURAL [K,N-seg] row-major via ldmatrix.trans.
// Segmented B supports fused N. BM=BN=128, BK=32, 8 warps, warp tile 64x32.
// ---------------------------------------------------------------------------
#define TG_ROW 40
#define TG_TILE (128 * TG_ROW)
#define TB_ROW 136
#define TB_TILE (32 * TB_ROW)

template<bool RELU, bool RES, bool F16OUT>
__global__ __launch_bounds__(256, 2)
void tc_gemm(const __half* __restrict__ Af, const __half* __restrict__ Bf,
             int seg_shift, size_t seg_stride,
             const float* __restrict__ bias, const float* __restrict__ res,
             float* __restrict__ C, __half* __restrict__ Cf,
             int M, int N, int K)
{
    __shared__ __half As[2][TG_TILE];
    __shared__ __half Bs[2][TB_TILE];
    const uint32_t sbA = smem_u32(&As[0][0]);
    const uint32_t sbB = smem_u32(&Bs[0][0]);
    const int tid = threadIdx.x;
    const int lane = tid & 31;
    const int wid = tid >> 5;
    const int wm = wid >> 2;
    const int wn = wid & 3;
    const int bm = blockIdx.y * 128;
    const int bn = blockIdx.x * 128;

    const int ld_b = 1 << seg_shift;
    const __half* Bseg = Bf + (size_t)(bn >> seg_shift) * seg_stride;
    const int bn_l = bn & (ld_b - 1);

    // A staging: thread -> (row 0..127, 16-elem half)
    const int srow = tid >> 1;
    const int shalf = (tid & 1) * 16;
    const uint32_t soA = (uint32_t)(srow * TG_ROW + shalf) * 2;
    const char* gA = (const char*)(Af + (size_t)(bm + srow) * K + shalf);

    // B staging: thread -> (k-row 0..31, 16-elem col chunk)
    const int brow = tid >> 3;
    const int bcol = (tid & 7) * 16;
    const uint32_t soB = (uint32_t)(brow * TB_ROW + bcol) * 2;
    const char* gB = (const char*)(Bseg + (size_t)brow * ld_b + bn_l + bcol);
    const size_t bstep = (size_t)32 * ld_b * 2;   // bytes per k-tile

    auto issue = [&](int s, int kt) {
        const uint32_t ad = sbA + (uint32_t)s * (TG_TILE * 2) + soA;
        const char* ga = gA + kt * 64;
        CPA16(ad,      ga);
        CPA16(ad + 16, ga + 16);
        const uint32_t bd = sbB + (uint32_t)s * (TB_TILE * 2) + soB;
        const char* gb = gB + (size_t)kt * bstep;
        CPA16(bd,      gb);
        CPA16(bd + 16, gb + 16);
    };

    const uint32_t a_off = (uint32_t)((lane & 15) * TG_ROW * 2 + (lane >> 4) * 16);
    const uint32_t b_off = (uint32_t)((lane & 15) * TB_ROW * 2 + (lane >> 4) * 16);
    uint32_t aAddr[4], bAddr[2];
    #pragma unroll
    for (int mt = 0; mt < 4; mt++)
        aAddr[mt] = sbA + (uint32_t)((wm * 64 + mt * 16) * TG_ROW * 2) + a_off;
    #pragma unroll
    for (int ng = 0; ng < 2; ng++)
        bAddr[ng] = sbB + (uint32_t)((wn * 32 + ng * 16) * 2) + b_off;

    float acc[4][4][4];
    #pragma unroll
    for (int mt = 0; mt < 4; mt++)
        #pragma unroll
        for (int nt = 0; nt < 4; nt++)
            #pragma unroll
            for (int r = 0; r < 4; r++) acc[mt][nt][r] = 0.f;

    issue(0, 0);
    CPA_COMMIT();

    const int nk = K >> 5;
    for (int kt = 0; kt < nk; kt++) {
        const int cur = kt & 1;
        const bool more = (kt + 1 < nk);
        if (more) issue(cur ^ 1, kt + 1);
        CPA_COMMIT();
        if (more) { CPA_WAIT1(); } else { CPA_WAIT0(); }
        __syncthreads();

        const uint32_t stA = (uint32_t)cur * (TG_TILE * 2);
        const uint32_t stB = (uint32_t)cur * (TB_TILE * 2);
        #pragma unroll
        for (int ks = 0; ks < 2; ks++) {
            const uint32_t kbA = stA + ks * 32;
            const uint32_t kbB = stB + (uint32_t)(ks * 16 * TB_ROW * 2);
            uint32_t ah[4][4], bt[2][4];
            #pragma unroll
            for (int mt = 0; mt < 4; mt++)
                ldm4(ah[mt], aAddr[mt] + kbA);
            #pragma unroll
            for (int ng = 0; ng < 2; ng++)
                ldm4t(bt[ng], bAddr[ng] + kbB);
            #pragma unroll
            for (int mt = 0; mt < 4; mt++) {
                #pragma unroll
                for (int nt = 0; nt < 4; nt++) {
                    const int ng = nt >> 1;
                    const int hf = (nt & 1) * 2;
                    mma16816(acc[mt][nt], ah[mt], &bt[ng][hf]);
                }
            }
        }
        __syncthreads();   // reads done before this buffer is refilled
    }

    const int er = lane >> 2;
    const int ec = (lane & 3) * 2;
    #pragma unroll
    for (int mt = 0; mt < 4; mt++) {
        const int row0 = bm + wm * 64 + mt * 16 + er;
        #pragma unroll
        for (int nt = 0; nt < 4; nt++) {
            const int col = bn + wn * 32 + nt * 8 + ec;
            float2 bv = *(const float2*)(bias + col);
            float v0 = acc[mt][nt][0] + bv.x;
            float v1 = acc[mt][nt][1] + bv.y;
            float v2 = acc[mt][nt][2] + bv.x;
            float v3 = acc[mt][nt][3] + bv.y;
            if (RELU) {
                v0 = fmaxf(v0, 0.f); v1 = fmaxf(v1, 0.f);
                v2 = fmaxf(v2, 0.f); v3 = fmaxf(v3, 0.f);
            }
            if (RES) {
                float2 r0 = *(const float2*)(res + (size_t)row0 * N + col);
                float2 r1 = *(const float2*)(res + (size_t)(row0 + 8) * N + col);
                v0 += r0.x; v1 += r0.y; v2 += r1.x; v3 += r1.y;
            }
            if (F16OUT) {
                *(__half2*)(Cf + (size_t)row0 * N + col)       = __floats2half2_rn(v0, v1);
                *(__half2*)(Cf + (size_t)(row0 + 8) * N + col) = __floats2half2_rn(v2, v3);
            } else {
                float2 o0 = {v0, v1};
                float2 o1 = {v2, v3};
                *(float2*)(C + (size_t)row0 * N + col) = o0;
                *(float2*)(C + (size_t)(row0 + 8) * N + col) = o1;
            }
        }
    }
}

// ---------------------------------------------------------------------------
// fp16 tensor-core flash attention with cp.async double-buffered K/V and
// ex2.approx.f16x2 softmax (round-16 version, unchanged).
// ---------------------------------------------------------------------------
#define QKST 72
#define L2E 1.4426950408889634f

__global__ __launch_bounds__(128)
void attn_tc_kernel(const __half* __restrict__ Qf, const __half* __restrict__ Kf,
                    const __half* __restrict__ Vf, __half* __restrict__ Of,
                    int ldq, int ldkv, int causal)
{
    __shared__ __half Qs[64 * QKST];
    __shared__ __half Ks[2][64 * QKST];
    __shared__ __half Vs[2][64 * QKST];
    const int qt = blockIdx.x;
    const int h  = blockIdx.y;
    const int b  = blockIdx.z;
    const int tid = threadIdx.x;
    const int lane = tid & 31;
    const int wid = tid >> 5;
    const size_t qrow0 = (size_t)b * TSEQ;

    const int sr = tid >> 1;
    const int shoff = (tid & 1) * 32;
    const uint32_t ksm[2] = {smem_u32(&Ks[0][0]), smem_u32(&Ks[1][0])};
    const uint32_t vsm[2] = {smem_u32(&Vs[0][0]), smem_u32(&Vs[1][0])};
    const uint32_t srowoff = (uint32_t)(sr * QKST + shoff) * 2;

    const int ktEnd = causal ? qt : (TSEQ / 64 - 1);

    auto issue_kv = [&](int s, int kt) {
        const size_t goff = (qrow0 + kt * 64 + sr) * (size_t)ldkv + h * DHEAD + shoff;
        const char* kg = (const char*)(Kf + goff);
        const char* vg = (const char*)(Vf + goff);
        const uint32_t kd = ksm[s] + srowoff;
        const uint32_t vd = vsm[s] + srowoff;
        CPA16(kd,      kg);
        CPA16(kd + 16, kg + 16);
        CPA16(kd + 32, kg + 32);
        CPA16(kd + 48, kg + 48);
        CPA16(vd,      vg);
        CPA16(vd + 16, vg + 16);
        CPA16(vd + 32, vg + 32);
        CPA16(vd + 48, vg + 48);
    };

    issue_kv(0, 0);
    CPA_COMMIT();
    {
        const __half2 sc = __floats2half2_rn(0.125f, 0.125f);
        const __half2* src = (const __half2*)(Qf + (qrow0 + qt * 64 + sr) * ldq
                                              + h * DHEAD + shoff);
        __half2* dst = (__half2*)(Qs + sr * QKST + shoff);
        #pragma unroll
        for (int i = 0; i < 16; i++) dst[i] = __hmul2(src[i], sc);
    }
    __syncthreads();

    const uint32_t a_off = (uint32_t)((lane & 15) * (QKST * 2) + (lane >> 4) * 16);
    const uint32_t b_off = (uint32_t)((((lane >> 4) << 3) + (lane & 7)) * (QKST * 2)
                                      + ((lane >> 3) & 1) * 16);

    uint32_t qfr[4][4];
    {
        const uint32_t qa = smem_u32(Qs) + (uint32_t)(wid * 16) * (QKST * 2) + a_off;
        #pragma unroll
        for (int ks = 0; ks < 4; ks++) ldm4(qfr[ks], qa + ks * 32);
    }

    float m0 = -INFINITY, m1 = -INFINITY, l0 = 0.f, l1 = 0.f;
    float ao[8][4];
    #pragma unroll
    for (int nt = 0; nt < 8; nt++)
        #pragma unroll
        for (int r = 0; r < 4; r++) ao[nt][r] = 0.f;

    const int gr = lane >> 2;
    const int gc = (lane & 3) * 2;
    const int row0 = qt * 64 + wid * 16 + gr;
    const int row1 = row0 + 8;

    for (int kt = 0; kt <= ktEnd; kt++) {
        const int buf = kt & 1;
        const bool more = (kt + 1 <= ktEnd);
        if (more) issue_kv(buf ^ 1, kt + 1);
        CPA_COMMIT();
        if (more) { CPA_WAIT1(); } else { CPA_WAIT0(); }
        __syncthreads();

        const uint32_t kbase = ksm[buf];
        const uint32_t vbase = vsm[buf];

        float s[8][4];
        #pragma unroll
        for (int nt = 0; nt < 8; nt++)
            #pragma unroll
            for (int r = 0; r < 4; r++) s[nt][r] = 0.f;
        #pragma unroll
        for (int g = 0; g < 4; g++) {
            #pragma unroll
            for (int ks = 0; ks < 4; ks++) {
                uint32_t bh[4];
                ldm4(bh, kbase + (uint32_t)(g * 16) * (QKST * 2) + b_off + ks * 32);
                mma16816(s[2 * g],     qfr[ks], &bh[0]);
                mma16816(s[2 * g + 1], qfr[ks], &bh[2]);
            }
        }

        const bool diag = causal && (kt == qt);
        float rmax0 = -INFINITY, rmax1 = -INFINITY;
        #pragma unroll
        for (int nt = 0; nt < 8; nt++) {
            if (diag) {
                const int c0 = kt * 64 + nt * 8 + gc;
                if (c0 > row0)     s[nt][0] = -INFINITY;
                if (c0 + 1 > row0) s[nt][1] = -INFINITY;
                if (c0 > row1)     s[nt][2] = -INFINITY;
                if (c0 + 1 > row1) s[nt][3] = -INFINITY;
            }
            rmax0 = fmaxf(rmax0, fmaxf(s[nt][0], s[nt][1]));
            rmax1 = fmaxf(rmax1, fmaxf(s[nt][2], s[nt][3]));
        }
        rmax0 = fmaxf(rmax0, __shfl_xor_sync(~0u, rmax0, 1));
        rmax0 = fmaxf(rmax0, __shfl_xor_sync(~0u, rmax0, 2));
        rmax1 = fmaxf(rmax1, __shfl_xor_sync(~0u, rmax1, 1));
        rmax1 = fmaxf(rmax1, __shfl_xor_sync(~0u, rmax1, 2));

        const float mn0 = fmaxf(m0, rmax0);
        const float mn1 = fmaxf(m1, rmax1);
        const float corr0 = __expf(m0 - mn0);
        const float corr1 = __expf(m1 - mn1);
        float rs0 = 0.f, rs1 = 0.f;
        uint32_t pf[8][2];
        #pragma unroll
        for (int nt = 0; nt < 8; nt++) {
            __half2 ta = __floats2half2_rn((s[nt][0] - mn0) * L2E,
                                           (s[nt][1] - mn0) * L2E);
            __half2 tb = __floats2half2_rn((s[nt][2] - mn1) * L2E,
                                           (s[nt][3] - mn1) * L2E);
            const uint32_t ua = ex2_f16x2(*(uint32_t*)&ta);
            const uint32_t ub = ex2_f16x2(*(uint32_t*)&tb);
            pf[nt][0] = ua;
            pf[nt][1] = ub;
            float2 fa = __half22float2(*(__half2*)&ua);
            float2 fb = __half22float2(*(__half2*)&ub);
            rs0 += fa.x + fa.y;
            rs1 += fb.x + fb.y;
        }
        rs0 += __shfl_xor_sync(~0u, rs0, 1);
        rs0 += __shfl_xor_sync(~0u, rs0, 2);
        rs1 += __shfl_xor_sync(~0u, rs1, 1);
        rs1 += __shfl_xor_sync(~0u, rs1, 2);
        l0 = l0 * corr0 + rs0;
        l1 = l1 * corr1 + rs1;
        m0 = mn0;
        m1 = mn1;
        #pragma unroll
        for (int nt = 0; nt < 8; nt++) {
            ao[nt][0] *= corr0; ao[nt][1] *= corr0;
            ao[nt][2] *= corr1; ao[nt][3] *= corr1;
        }

        #pragma unroll
        for (int kc = 0; kc < 4; kc++) {
            uint32_t pa[4] = {pf[2 * kc][0], pf[2 * kc][1],
                              pf[2 * kc + 1][0], pf[2 * kc + 1][1]};
            const uint32_t vrow = vbase + (uint32_t)(kc * 16) * (QKST * 2) + a_off;
            #pragma unroll
            for (int g = 0; g < 4; g++) {
                uint32_t bv[4];
                ldm4t(bv, vrow + g * 32);
                mma16816(ao[2 * g],     pa, &bv[0]);
                mma16816(ao[2 * g + 1], pa, &bv[2]);
            }
        }
        __syncthreads();
    }

    const float inv0 = 1.f / l0;
    const float inv1 = 1.f / l1;
    const size_t o0 = (qrow0 + row0) * D_MODEL + h * DHEAD;
    const size_t o1 = (qrow0 + row1) * D_MODEL + h * DHEAD;
    #pragma unroll
    for (int nt = 0; nt < 8; nt++) {
        const int col = nt * 8 + gc;
        *(__half2*)(Of + o0 + col) = __floats2half2_rn(ao[nt][0] * inv0, ao[nt][1] * inv0);
        *(__half2*)(Of + o1 + col) = __floats2half2_rn(ao[nt][2] * inv1, ao[nt][3] * inv1);
    }
}

// ---------------------------------------------------------------------------
// Host orchestration
// ---------------------------------------------------------------------------
extern "C" void kernel_launch(void* const* d_in, const int* in_sizes, int n_in,
                              void* d_out, int out_size)
{
    (void)in_sizes; (void)n_in; (void)out_size;
    const float* x     = (const float*)d_in[0];
    const float* src_x = (const float*)d_in[1];
    const float* ln1_g = (const float*)d_in[4];
    const float* ln1_b = (const float*)d_in[5];
    const float* ln2_g = (const float*)d_in[6];
    const float* ln2_b = (const float*)d_in[7];
    const float* ln3_g = (const float*)d_in[8];
    const float* ln3_b = (const float*)d_in[9];
    const float* W[8];
    for (int i = 0; i < 8; i++) W[i] = (const float*)d_in[10 + i];
    const float* Bv[8];
    for (int i = 0; i < 8; i++) Bv[i] = (const float*)d_in[18 + i];
    const float* ff_w1 = (const float*)d_in[26];
    const float* ff_b1 = (const float*)d_in[27];
    const float* ff_w2 = (const float*)d_in[28];
    const float* ff_b2 = (const float*)d_in[29];
    float* out = (float*)d_out;

    float *x1, *x2, *bqkv, *bkv;
    cudaGetSymbolAddress((void**)&x1, g_x1);
    cudaGetSymbolAddress((void**)&x2, g_x2);
    cudaGetSymbolAddress((void**)&bqkv, g_bqkv);
    cudaGetSymbolAddress((void**)&bkv,  g_bkv);
    __half *wf, *af, *sf, *ff, *qkv;
    cudaGetSymbolAddress((void**)&wf,  g_wf16);
    cudaGetSymbolAddress((void**)&af,  g_af16);
    cudaGetSymbolAddress((void**)&sf,  g_sf16);
    cudaGetSymbolAddress((void**)&ff,  g_ff16);
    cudaGetSymbolAddress((void**)&qkv, g_qkv);

    const dim3 gQKV(3 * D_MODEL / 128, N_ROWS / 128);   // (24, 32)
    const dim3 gKV (2 * D_MODEL / 128, N_ROWS / 128);   // (16, 32)
    const dim3 gD  (D_MODEL / 128, N_ROWS / 128);       // (8, 32)
    const dim3 gF1 (DFF_   / 128, N_ROWS / 128);        // (32, 32)
    const dim3 gAtt(TSEQ / 64, NHEAD, BATCH);
    const size_t SEG = (size_t)1 << 20;

    // ---- batched convert: 8 square weights + ff_w1 + ff_w2 + src_x ----
    {
        CvtJob j;
        for (int i = 0; i < 8; i++) { j.s[i] = W[i]; j.d[i] = wf + (i << 20); }
        for (int i = 0; i < 4; i++) {
            j.s[8  + i] = ff_w1 + i * (1 << 20); j.d[8  + i] = wf + W1_OFF + (i << 20);
            j.s[12 + i] = ff_w2 + i * (1 << 20); j.d[12 + i] = wf + W2_OFF + (i << 20);
            j.s[16 + i] = src_x + i * (1 << 20); j.d[16 + i] = sf + (i << 20);
        }
        dim3 gc(1024, 1, 20);
        cvt_kernel<<<gc, 256>>>(j);
    }
    catbias_kernel<<<20, 256>>>(Bv[0], Bv[1], Bv[2], Bv[5], Bv[6], bqkv, bkv);
    ln_f16_kernel<<<N_ROWS, 256>>>(x, ln1_g, ln1_b, af);

    // ---- self-attention block (fused QKV) ----
    tc_gemm<false, false, true><<<gQKV, 256>>>(af, wf + WQ_OFF, 10, SEG, bqkv, nullptr, nullptr, qkv, N_ROWS, 3 * D_MODEL, D_MODEL);
    attn_tc_kernel<<<gAtt, 128>>>(qkv, qkv + D_MODEL, qkv + 2 * D_MODEL, af,
                                  3 * D_MODEL, 3 * D_MODEL, 1);
    tc_gemm<false, true, false><<<gD, 256>>>(af, wf + WO_OFF, 10, SEG, Bv[3], x, x1, nullptr, N_ROWS, D_MODEL, D_MODEL);

    // ---- cross-attention block (fused KV) ----
    ln_f16_kernel<<<N_ROWS, 256>>>(x1, ln2_g, ln2_b, af);
    tc_gemm<false, false, true><<<gD, 256>>>(af, wf + CQ_OFF, 10, SEG, Bv[4], nullptr, nullptr, ff, N_ROWS, D_MODEL, D_MODEL);
    tc_gemm<false, false, true><<<gKV, 256>>>(sf, wf + CK_OFF, 10, SEG, bkv, nullptr, nullptr, qkv, N_ROWS, 2 * D_MODEL, D_MODEL);
    attn_tc_kernel<<<gAtt, 128>>>(ff, qkv, qkv + D_MODEL, af,
                                  D_MODEL, 2 * D_MODEL, 0);
    tc_gemm<false, true, false><<<gD, 256>>>(af, wf + CO_OFF, 10, SEG, Bv[7], x1, x2, nullptr, N_ROWS, D_MODEL, D_MODEL);

    // ---- FFN block ----
    ln_f16_kernel<<<N_ROWS, 256>>>(x2, ln3_g, ln3_b, af);
    tc_gemm<true, false, true><<<gF1, 256>>>(af, wf + W1_OFF, 12, SEG, ff_b1, nullptr, nullptr, ff, N_ROWS, DFF_, D_MODEL);
    tc_gemm<false, true, false><<<gD, 256>>>(ff, wf + W2_OFF, 10, SEG, ff_b2, x2, out, nullptr, N_ROWS, D_MODEL, DFF_);
}